// round 13
// baseline (speedup 1.0000x reference)
#include <cuda_runtime.h>
#include <cuda_fp16.h>
#include <cstdint>

// Problem constants (fixed by dataset)
#define NV 100000
#define EV 1600000
#define FV 512
#define HV 256
#define NB_SCAN ((NV + 255) / 256)   // 391

// ---------------- scratch (static device globals; no allocation) ----------------
__device__ int   g_out_deg[NV];
__device__ int   g_in_deg[NV];
__device__ float g_norm_src[NV];
__device__ float g_norm_dst[NV];
__device__ int   g_offsets[NV];      // block-local exclusive prefix (needs + g_part[i>>8])
__device__ int   g_cursor[NV];
__device__ int   g_part[NB_SCAN];
__device__ int   g_sorted_src[EV];
__device__ __align__(16) __half g_yh[(size_t)NV * HV];  // pre-aggregation activations (fp16)
__device__ __align__(16) __half g_hh[(size_t)NV * HV];  // post-aggregation activations (fp16)
__device__ __align__(16) uint32_t g_wt1[HV * (FV / 2)]; // W1^T as fp16x2: [n][k/2]
__device__ __align__(16) uint32_t g_wt2[HV * (HV / 2)]; // W2^T as fp16x2
__device__ float g_pooled[3 * HV];
__device__ float g_fd[2 * FV];

// ---------------- init + weight transpose + fd bias seed ----------------
__global__ void k_init(const float* __restrict__ W1, const float* __restrict__ W2,
                       const float* __restrict__ bg) {
    int i = blockIdx.x * blockDim.x + threadIdx.x;
    if (i < NV) { g_out_deg[i] = 0; g_in_deg[i] = 0; g_cursor[i] = 0; }
    if (i < HV) { g_pooled[i] = 0.0f; g_pooled[HV + i] = __int_as_float(0xff800000); } // -inf
    if (i < 2 * FV) g_fd[i] = bg[i];
    if (i < HV * (FV / 2)) {
        int n  = i / (FV / 2);
        int kp = i % (FV / 2);
        __half2 h = __floats2half2_rn(W1[(size_t)(2 * kp) * HV + n],
                                      W1[(size_t)(2 * kp + 1) * HV + n]);
        g_wt1[i] = *(uint32_t*)&h;
    }
    if (i < HV * (HV / 2)) {
        int n  = i / (HV / 2);
        int kp = i % (HV / 2);
        __half2 h = __floats2half2_rn(W2[(size_t)(2 * kp) * HV + n],
                                      W2[(size_t)(2 * kp + 1) * HV + n]);
        g_wt2[i] = *(uint32_t*)&h;
    }
}

__global__ void k_deg(const int* __restrict__ src, const int* __restrict__ dst) {
    int e = blockIdx.x * blockDim.x + threadIdx.x;
    if (e < EV) {
        atomicAdd(&g_out_deg[src[e]], 1);
        atomicAdd(&g_in_deg[dst[e]], 1);
    }
}

// ---------------- scan1 + norms (fused: same grid, both depend only on k_deg) -----
__global__ void k_scan1() {
    __shared__ int s[256];
    int t = threadIdx.x;
    int i = blockIdx.x * 256 + t;
    int v = (i < NV) ? g_in_deg[i] : 0;
    // fused k_norm
    if (i < NV) {
        g_norm_src[i] = rsqrtf(fmaxf((float)g_out_deg[i], 1.0f));
        g_norm_dst[i] = rsqrtf(fmaxf((float)v, 1.0f));
    }
    s[t] = v;
    __syncthreads();
    #pragma unroll
    for (int off = 1; off < 256; off <<= 1) {
        int x = (t >= off) ? s[t - off] : 0;
        __syncthreads();
        s[t] += x;
        __syncthreads();
    }
    if (i < NV) g_offsets[i] = s[t] - v;        // block-local exclusive
    if (t == 255) g_part[blockIdx.x] = s[255];
}

__global__ void k_scan2() {
    __shared__ int s[512];
    int t = threadIdx.x;
    int v = (t < NB_SCAN) ? g_part[t] : 0;
    s[t] = v;
    __syncthreads();
    #pragma unroll
    for (int off = 1; off < 512; off <<= 1) {
        int x = (t >= off) ? s[t - off] : 0;
        __syncthreads();
        s[t] += x;
        __syncthreads();
    }
    if (t < NB_SCAN) g_part[t] = s[t] - v;      // exclusive block prefix
}

// scatter edges into CSR-by-dst (scan3 folded in: full offset = g_offsets + g_part)
__global__ void k_scatter(const int* __restrict__ src, const int* __restrict__ dst) {
    int e = blockIdx.x * blockDim.x + threadIdx.x;
    if (e < EV) {
        int d = dst[e];
        int p = atomicAdd(&g_cursor[d], 1);
        g_sorted_src[g_offsets[d] + g_part[d >> 8] + p] = src[e];
    }
}

// ---------------- fp16 mma GEMM: BK=32, single sync/tile, ldmatrix + cp.async ----
#define SRS2 20   // smem row stride in 32-bit words (16 data + 4 pad; ldsm conflict-free)

__device__ __forceinline__ void mma_f16(float* c, const uint32_t* a, const uint32_t* b) {
    asm volatile(
        "mma.sync.aligned.m16n8k16.row.col.f32.f16.f16.f32 "
        "{%0,%1,%2,%3}, {%4,%5,%6,%7}, {%8,%9}, {%0,%1,%2,%3};"
        : "+f"(c[0]), "+f"(c[1]), "+f"(c[2]), "+f"(c[3])
        : "r"(a[0]), "r"(a[1]), "r"(a[2]), "r"(a[3]), "r"(b[0]), "r"(b[1]));
}

__device__ __forceinline__ void ldsm_x4(uint32_t* r, uint32_t saddr) {
    asm volatile("ldmatrix.sync.aligned.m8n8.x4.shared.b16 {%0,%1,%2,%3}, [%4];"
                 : "=r"(r[0]), "=r"(r[1]), "=r"(r[2]), "=r"(r[3]) : "r"(saddr));
}

__device__ __forceinline__ void cp_async16(uint32_t dst, const void* src) {
    asm volatile("cp.async.ca.shared.global [%0], [%1], 16;" :: "r"(dst), "l"(src) : "memory");
}

__device__ __forceinline__ void sts_v4(uint32_t addr, uint4 w) {
    asm volatile("st.shared.v4.b32 [%0], {%1,%2,%3,%4};"
                 :: "r"(addr), "r"(w.x), "r"(w.y), "r"(w.z), "r"(w.w) : "memory");
}

template <bool AHALF>
__global__ __launch_bounds__(256, 2) void k_gemm(const float*  __restrict__ Af,
                                                 const __half* __restrict__ Ah,
                                                 const uint32_t* __restrict__ Wt,
                                                 __half* __restrict__ C,
                                                 int M, int K) {
    __shared__ uint32_t As[2][128 * SRS2];   // [m][kp 0..15] packed fp16x2
    __shared__ uint32_t Bs[2][128 * SRS2];   // [n][kp 0..15]

    int tid  = threadIdx.x;
    int brow = blockIdx.y * 128;
    int bcol = blockIdx.x * 128;
    int Kp   = K >> 1;                       // K in fp16x2 words

    uint32_t as_base = (uint32_t)__cvta_generic_to_shared(&As[0][0]);
    uint32_t bs_base = (uint32_t)__cvta_generic_to_shared(&Bs[0][0]);
    const uint32_t BUFB = 128 * SRS2 * 4;    // bytes per buffer

    // ---- A mapping: row = tid/2, 16 k-halves per thread ----
    int arow  = tid >> 1;
    int ahalf = tid & 1;                     // 0: k 0..15 of tile, 1: k 16..31
    int gr = brow + arow;
    bool v = gr < M;
    const float*    Apf = AHALF ? nullptr : (Af + (size_t)(v ? gr : 0) * K  + ahalf * 16);
    const uint32_t* Aph = AHALF ? ((const uint32_t*)Ah + (size_t)(v ? gr : 0) * Kp + ahalf * 8) : nullptr;
    uint32_t a_st = as_base + (arow * SRS2 + ahalf * 8) * 4;

    // ---- B cp.async mapping: n = tid/2, 32B (16 k-halves) per thread (2x16B) ----
    int bn    = tid >> 1;
    int bhalf = tid & 1;
    const uint32_t* Bp = Wt + (size_t)(bcol + bn) * Kp + bhalf * 8;
    uint32_t b_st = bs_base + (bn * SRS2 + bhalf * 8) * 4;

    // ---- warp tiling: 8 warps (4m x 2n), each 32x64 ----
    int wid  = tid >> 5, lane = tid & 31;
    int wm = (wid & 3) * 32;
    int wn = (wid >> 2) * 64;
    int r  = lane >> 2;
    int cq = lane & 3;

    // ldmatrix byte offsets within a buffer (ks adds 32B = 8 words)
    uint32_t a_ld_off0 = ((wm + (lane & 15)) * SRS2 + (lane >> 4) * 4) * 4;
    uint32_t a_ld_off1 = ((wm + 16 + (lane & 15)) * SRS2 + (lane >> 4) * 4) * 4;
    int bn_in = (lane & 7) + ((lane >> 4) << 3);
    int bk_in = (lane >> 3) & 1;
    uint32_t b_ld_off[4];
    #pragma unroll
    for (int j = 0; j < 4; j++)
        b_ld_off[j] = ((wn + j * 16 + bn_in) * SRS2 + bk_in * 4) * 4;

    float acc[2][8][4];
    #pragma unroll
    for (int i = 0; i < 2; i++)
        #pragma unroll
        for (int j = 0; j < 8; j++)
            #pragma unroll
            for (int q = 0; q < 4; q++) acc[i][j][q] = 0.0f;

    float4 pa[4];   // f32 A prefetch regs (GEMM1 path only)

    // prologue: tile 0 loads
    if (AHALF) {
        cp_async16(a_st,      Aph);
        cp_async16(a_st + 16, Aph + 4);
    } else {
        #pragma unroll
        for (int i = 0; i < 4; i++)
            pa[i] = v ? *(const float4*)(Apf + i * 4) : make_float4(0,0,0,0);
    }
    cp_async16(b_st,      Bp);
    cp_async16(b_st + 16, Bp + 4);
    asm volatile("cp.async.commit_group;" ::: "memory");

    int buf = 0;
    for (int k0 = 0; k0 < K; k0 += 32) {
        if (!AHALF) {
            uint32_t ast = a_st + buf * BUFB;
            __half2 h0 = __floats2half2_rn(pa[0].x, pa[0].y);
            __half2 h1 = __floats2half2_rn(pa[0].z, pa[0].w);
            __half2 h2 = __floats2half2_rn(pa[1].x, pa[1].y);
            __half2 h3 = __floats2half2_rn(pa[1].z, pa[1].w);
            __half2 h4 = __floats2half2_rn(pa[2].x, pa[2].y);
            __half2 h5 = __floats2half2_rn(pa[2].z, pa[2].w);
            __half2 h6 = __floats2half2_rn(pa[3].x, pa[3].y);
            __half2 h7 = __floats2half2_rn(pa[3].z, pa[3].w);
            sts_v4(ast,      make_uint4(*(uint32_t*)&h0, *(uint32_t*)&h1, *(uint32_t*)&h2, *(uint32_t*)&h3));
            sts_v4(ast + 16, make_uint4(*(uint32_t*)&h4, *(uint32_t*)&h5, *(uint32_t*)&h6, *(uint32_t*)&h7));
        }

        asm volatile("cp.async.wait_group 0;" ::: "memory");   // tile k0 async loads landed
        __syncthreads();                                       // single barrier per tile

        int kn = k0 + 32;
        if (kn < K) {
            if (AHALF) {
                uint32_t adst = a_st + (buf ^ 1) * BUFB;
                cp_async16(adst,      Aph + (kn >> 1));
                cp_async16(adst + 16, Aph + (kn >> 1) + 4);
            } else {
                #pragma unroll
                for (int i = 0; i < 4; i++)
                    pa[i] = v ? *(const float4*)(Apf + kn + i * 4) : make_float4(0,0,0,0);
            }
            uint32_t bdst = b_st + (buf ^ 1) * BUFB;
            cp_async16(bdst,      Bp + (kn >> 1));
            cp_async16(bdst + 16, Bp + (kn >> 1) + 4);
            asm volatile("cp.async.commit_group;" ::: "memory");
        }

        // compute: 2 k-steps of m16n8k16
        uint32_t abase = as_base + buf * BUFB;
        uint32_t bbase = bs_base + buf * BUFB;
        #pragma unroll
        for (int ks = 0; ks < 2; ks++) {
            uint32_t koff = ks * 32;   // 8 words
            uint32_t a[2][4], b[8][2];
            ldsm_x4(a[0], abase + a_ld_off0 + koff);
            ldsm_x4(a[1], abase + a_ld_off1 + koff);
            #pragma unroll
            for (int j = 0; j < 4; j++) {
                uint32_t rr[4];
                ldsm_x4(rr, bbase + b_ld_off[j] + koff);
                b[2*j][0]   = rr[0];
                b[2*j][1]   = rr[1];
                b[2*j+1][0] = rr[2];
                b[2*j+1][1] = rr[3];
            }
            #pragma unroll
            for (int mt = 0; mt < 2; mt++)
                #pragma unroll
                for (int nt = 0; nt < 8; nt++)
                    mma_f16(acc[mt][nt], a[mt], b[nt]);
        }
        buf ^= 1;
        // no second __syncthreads(): next store targets buf^1, last read 2 iters ago
    }

    // ---- epilogue: scale by norm_src[row], convert fp16 RN, store ----
    #pragma unroll
    for (int mt = 0; mt < 2; mt++) {
        int row0 = brow + wm + mt * 16 + r;
        int row1 = row0 + 8;
        float s0 = (row0 < M) ? g_norm_src[row0] : 0.0f;
        float s1 = (row1 < M) ? g_norm_src[row1] : 0.0f;
        #pragma unroll
        for (int nt = 0; nt < 8; nt++) {
            int col = bcol + wn + nt * 8 + cq * 2;
            if (row0 < M)
                *(__half2*)(C + (size_t)row0 * HV + col) =
                    __floats2half2_rn(acc[mt][nt][0] * s0, acc[mt][nt][1] * s0);
            if (row1 < M)
                *(__half2*)(C + (size_t)row1 * HV + col) =
                    __floats2half2_rn(acc[mt][nt][2] * s1, acc[mt][nt][3] * s1);
        }
    }
}

// ---------------- aggregation: warp-per-node, uint4 (16B) lane loads ----------------
__global__ void k_agg(const __half* __restrict__ Y, const float* __restrict__ bias,
                      __half* __restrict__ O) {
    int node = blockIdx.x * 4 + (threadIdx.x >> 5);
    if (node >= NV) return;
    int lane = threadIdx.x & 31;            // 8 cols per lane via uint4
    int start = g_offsets[node] + g_part[node >> 8];
    int cnt   = g_in_deg[node];
    const uint4* Yv = (const uint4*)Y;      // row stride = 32 uint4

    float acc[4][8];
    #pragma unroll
    for (int i = 0; i < 4; i++)
        #pragma unroll
        for (int j = 0; j < 8; j++) acc[i][j] = 0.0f;

    int e = 0;
    for (; e + 4 <= cnt; e += 4) {
        int s0 = g_sorted_src[start + e];
        int s1 = g_sorted_src[start + e + 1];
        int s2 = g_sorted_src[start + e + 2];
        int s3 = g_sorted_src[start + e + 3];
        uint4 u0 = Yv[(size_t)s0 * 32 + lane];
        uint4 u1 = Yv[(size_t)s1 * 32 + lane];
        uint4 u2 = Yv[(size_t)s2 * 32 + lane];
        uint4 u3 = Yv[(size_t)s3 * 32 + lane];
        #pragma unroll
        for (int w = 0; w < 4; w++) {
            float2 f0 = __half22float2(*((__half2*)&u0 + w));
            float2 f1 = __half22float2(*((__half2*)&u1 + w));
            float2 f2 = __half22float2(*((__half2*)&u2 + w));
            float2 f3 = __half22float2(*((__half2*)&u3 + w));
            acc[0][2*w]   += f0.x; acc[0][2*w+1] += f0.y;
            acc[1][2*w]   += f1.x; acc[1][2*w+1] += f1.y;
            acc[2][2*w]   += f2.x; acc[2][2*w+1] += f2.y;
            acc[3][2*w]   += f3.x; acc[3][2*w+1] += f3.y;
        }
    }
    for (; e < cnt; e++) {
        int s0 = g_sorted_src[start + e];
        uint4 u0 = Yv[(size_t)s0 * 32 + lane];
        #pragma unroll
        for (int w = 0; w < 4; w++) {
            float2 f0 = __half22float2(*((__half2*)&u0 + w));
            acc[0][2*w]   += f0.x; acc[0][2*w+1] += f0.y;
        }
    }
    #pragma unroll
    for (int j = 0; j < 8; j++) acc[0][j] += acc[1][j] + acc[2][j] + acc[3][j];

    float nd = g_norm_dst[node];
    float4 bb0 = *(const float4*)(bias + lane * 8);
    float4 bb1 = *(const float4*)(bias + lane * 8 + 4);
    float o[8];
    o[0] = acc[0][0] * nd + bb0.x;
    o[1] = acc[0][1] * nd + bb0.y;
    o[2] = acc[0][2] * nd + bb0.z;
    o[3] = acc[0][3] * nd + bb0.w;
    o[4] = acc[0][4] * nd + bb1.x;
    o[5] = acc[0][5] * nd + bb1.y;
    o[6] = acc[0][6] * nd + bb1.z;
    o[7] = acc[0][7] * nd + bb1.w;
    #pragma unroll
    for (int j = 0; j < 8; j++) o[j] = (o[j] >= 0.0f) ? o[j] : 0.01f * o[j];

    __half2 h0 = __floats2half2_rn(o[0], o[1]);
    __half2 h1 = __floats2half2_rn(o[2], o[3]);
    __half2 h2 = __floats2half2_rn(o[4], o[5]);
    __half2 h3 = __floats2half2_rn(o[6], o[7]);
    *(uint4*)(O + (size_t)node * HV + lane * 8) =
        make_uint4(*(uint32_t*)&h0, *(uint32_t*)&h1, *(uint32_t*)&h2, *(uint32_t*)&h3);
}

// ---------------- pooling (fused pick: block 0 also copies h[node_index]) ----------
__device__ __forceinline__ void atomicMaxF(float* addr, float val) {
    int* ia = (int*)addr;
    int old = *ia;
    while (__int_as_float(old) < val) {
        int assumed = old;
        old = atomicCAS(ia, assumed, __float_as_int(val));
        if (old == assumed) break;
    }
}

__global__ void k_pool(const __half* __restrict__ H, const int* __restrict__ node_index) {
    int t = threadIdx.x;  // 256
    if (blockIdx.x == 0) {
        int ni = node_index[0];
        g_pooled[2 * HV + t] = __half2float(H[(size_t)ni * HV + t]);
    }
    float sum = 0.0f;
    float mx  = __int_as_float(0xff800000);
    for (int r = blockIdx.x; r < NV; r += gridDim.x) {
        float v = __half2float(H[(size_t)r * HV + t]);
        sum += v;
        mx = fmaxf(mx, v);
    }
    atomicAdd(&g_pooled[t], sum);
    atomicMaxF(&g_pooled[HV + t], mx);
}

// ---------------- head GEMV (split-k, 32 blocks, atomic partials; bias pre-seeded) ----
__global__ void k_gemv(const float* __restrict__ Wg) {
    __shared__ float sp[96];
    int t = threadIdx.x;              // 256
    int jb = blockIdx.x & 3;          // output block
    int kb = blockIdx.x >> 2;         // k chunk (8 x 96)
    for (int i = t; i < 96; i += 256) sp[i] = g_pooled[kb * 96 + i];
    __syncthreads();
    int j = jb * 256 + t;
    float acc = 0.0f;
    #pragma unroll 8
    for (int k = 0; k < 96; k++)
        acc += sp[k] * Wg[(size_t)(kb * 96 + k) * (2 * FV) + j];
    atomicAdd(&g_fd[j], acc);
}

// ---------------- epilogue: reparam + log_prob ----------------
__global__ void k_final(const float* __restrict__ eps, float* __restrict__ out) {
    __shared__ float red[FV];
    int t = threadIdx.x;  // 512
    float mu = g_fd[t];
    float sg = fabsf(g_fd[FV + t]);
    float fn = mu + sg * eps[t];
    out[t]          = fn;
    out[FV + t]     = mu;
    out[2 * FV + t] = sg;
    float z = (fn - mu) / sg;
    const float half_log2pi = 0.9189385332046727f;
    float term = -0.5f * z * z - logf(sg) - half_log2pi;
    red[t] = term;
    __syncthreads();
    #pragma unroll
    for (int o = 256; o > 0; o >>= 1) {
        if (t < o) red[t] += red[t + o];
        __syncthreads();
    }
    if (t == 0) out[3 * FV] = red[0] / (float)FV;
}

// ---------------- launch ----------------
extern "C" void kernel_launch(void* const* d_in, const int* in_sizes, int n_in,
                              void* d_out, int out_size) {
    const float* feat       = (const float*)d_in[0];
    const int*   src        = (const int*)  d_in[1];
    const int*   dst        = (const int*)  d_in[2];
    const int*   node_index = (const int*)  d_in[3];
    const float* W1         = (const float*)d_in[4];
    const float* b1         = (const float*)d_in[5];
    const float* W2         = (const float*)d_in[6];
    const float* b2         = (const float*)d_in[7];
    const float* Wg         = (const float*)d_in[8];
    const float* bg         = (const float*)d_in[9];
    const float* eps        = (const float*)d_in[10];
    float*       out        = (float*)d_out;

    void *yp_v, *hp_v, *w1p_v, *w2p_v;
    cudaGetSymbolAddress(&yp_v, g_yh);
    cudaGetSymbolAddress(&hp_v, g_hh);
    cudaGetSymbolAddress(&w1p_v, g_wt1);
    cudaGetSymbolAddress(&w2p_v, g_wt2);
    __half*   yp  = (__half*)yp_v;
    __half*   hp  = (__half*)hp_v;
    uint32_t* w1p = (uint32_t*)w1p_v;
    uint32_t* w2p = (uint32_t*)w2p_v;

    dim3 gemm_grid(2, (NV + 127) / 128);
    int agg_grid = (NV + 3) / 4;

    k_init<<<(NV + 255) / 256, 256>>>(W1, W2, bg);
    k_deg<<<(EV + 255) / 256, 256>>>(src, dst);
    k_scan1<<<NB_SCAN, 256>>>();
    // GEMM1 at launch slot #4 (index 3) for the fixed-index ncu capture
    k_gemm<false><<<gemm_grid, 256>>>(feat, nullptr, w1p, yp, NV, FV);
    k_scan2<<<1, 512>>>();
    k_scatter<<<(EV + 255) / 256, 256>>>(src, dst);

    k_agg<<<agg_grid, 128>>>(yp, b1, hp);
    k_gemm<true><<<gemm_grid, 256>>>(nullptr, hp, w2p, yp, NV, HV);
    k_agg<<<agg_grid, 128>>>(yp, b2, hp);

    k_pool<<<256, 256>>>(hp, node_index);
    k_gemv<<<32, 256>>>(Wg);
    k_final<<<1, 512>>>(eps, out);
}

// round 14
// speedup vs baseline: 1.0162x; 1.0162x over previous
#include <cuda_runtime.h>
#include <cuda_fp16.h>
#include <cstdint>

// Problem constants (fixed by dataset)
#define NV 100000
#define EV 1600000
#define FV 512
#define HV 256
#define NB_SCAN ((NV + 255) / 256)   // 391
#define NT_W1 64                      // (512/64) x (256/32) transpose tiles
#define NT_W2 32                      // (256/64) x (256/32)

// ---------------- scratch (static device globals; no allocation) ----------------
__device__ int   g_out_deg[NV];
__device__ int   g_in_deg[NV];
__device__ float g_norm_src[NV];
__device__ float g_norm_dst[NV];
__device__ int   g_offsets[NV];
__device__ int   g_cursor[NV];
__device__ int   g_part[NB_SCAN];
__device__ int   g_sorted_src[EV];
__device__ __align__(16) __half g_yh[(size_t)NV * HV];  // pre-aggregation activations (fp16)
__device__ __align__(16) __half g_hh[(size_t)NV * HV];  // post-aggregation activations (fp16)
__device__ __align__(16) uint32_t g_wt1[HV * (FV / 2)]; // W1^T as fp16x2: [n][k/2]
__device__ __align__(16) uint32_t g_wt2[HV * (HV / 2)]; // W2^T as fp16x2
__device__ float g_pooled[3 * HV];
__device__ float g_fd[2 * FV];

// ---------------- init: counters + fd bias seed + TILED weight transpose ----------
// blocks [0, NB_SCAN): zero counters / seed pooled+fd
// blocks [NB_SCAN, NB_SCAN+96): coalesced 64k x 32n transpose tiles of W1 / W2
__global__ void k_init(const float* __restrict__ W1, const float* __restrict__ W2,
                       const float* __restrict__ bg) {
    int b = blockIdx.x;
    if (b >= NB_SCAN) {
        __shared__ float s[32][65];          // s[col(n)][row(k)] — conflict-free
        int tile = b - NB_SCAN;
        const float* W;
        uint32_t* Wtp;
        int K;
        if (tile < NT_W1) { W = W1; Wtp = g_wt1; K = FV; }
        else              { tile -= NT_W1; W = W2; Wtp = g_wt2; K = HV; }
        int kt = tile >> 3;                  // 8 n-tiles per k-row of tiles
        int nt = tile & 7;
        int k0 = kt * 64, n0 = nt * 32;
        int t = threadIdx.x;
        // load 64 x 32 floats, coalesced per 32-lane row
        #pragma unroll
        for (int j = 0; j < 8; j++) {
            int idx = t + j * 256;
            int row = idx >> 5;              // k within tile
            int col = idx & 31;              // n within tile
            s[col][row] = W[(size_t)(k0 + row) * HV + n0 + col];
        }
        __syncthreads();
        // write 32 n-rows x 32 kp words, coalesced per 32-lane row
        int Kp = K >> 1;
        #pragma unroll
        for (int j = 0; j < 4; j++) {
            int idx = t + j * 256;
            int n  = idx >> 5;
            int kp = idx & 31;
            __half2 h = __floats2half2_rn(s[n][2 * kp], s[n][2 * kp + 1]);
            Wtp[(size_t)(n0 + n) * Kp + (k0 >> 1) + kp] = *(uint32_t*)&h;
        }
        return;
    }
    int i = b * blockDim.x + threadIdx.x;
    if (i < NV) { g_out_deg[i] = 0; g_in_deg[i] = 0; g_cursor[i] = 0; }
    if (i < HV) { g_pooled[i] = 0.0f; g_pooled[HV + i] = __int_as_float(0xff800000); } // -inf
    if (i < 2 * FV) g_fd[i] = bg[i];
}

__global__ void k_deg(const int* __restrict__ src, const int* __restrict__ dst) {
    int e = blockIdx.x * blockDim.x + threadIdx.x;
    if (e < EV) {
        atomicAdd(&g_out_deg[src[e]], 1);
        atomicAdd(&g_in_deg[dst[e]], 1);
    }
}

__global__ void k_norm() {
    int i = blockIdx.x * blockDim.x + threadIdx.x;
    if (i < NV) {
        g_norm_src[i] = rsqrtf(fmaxf((float)g_out_deg[i], 1.0f));
        g_norm_dst[i] = rsqrtf(fmaxf((float)g_in_deg[i], 1.0f));
    }
}

// ---------------- exclusive scan of in_deg -> offsets ----------------
__global__ void k_scan1() {
    __shared__ int s[256];
    int t = threadIdx.x;
    int i = blockIdx.x * 256 + t;
    int v = (i < NV) ? g_in_deg[i] : 0;
    s[t] = v;
    __syncthreads();
    #pragma unroll
    for (int off = 1; off < 256; off <<= 1) {
        int x = (t >= off) ? s[t - off] : 0;
        __syncthreads();
        s[t] += x;
        __syncthreads();
    }
    if (i < NV) g_offsets[i] = s[t] - v;
    if (t == 255) g_part[blockIdx.x] = s[255];
}

__global__ void k_scan2() {
    __shared__ int s[512];
    int t = threadIdx.x;
    int v = (t < NB_SCAN) ? g_part[t] : 0;
    s[t] = v;
    __syncthreads();
    #pragma unroll
    for (int off = 1; off < 512; off <<= 1) {
        int x = (t >= off) ? s[t - off] : 0;
        __syncthreads();
        s[t] += x;
        __syncthreads();
    }
    if (t < NB_SCAN) g_part[t] = s[t] - v;
}

__global__ void k_scan3() {
    int t = threadIdx.x;
    int i = blockIdx.x * 256 + t;
    if (i < NV) g_offsets[i] += g_part[blockIdx.x];
}

__global__ void k_scatter(const int* __restrict__ src, const int* __restrict__ dst) {
    int e = blockIdx.x * blockDim.x + threadIdx.x;
    if (e < EV) {
        int d = dst[e];
        int p = atomicAdd(&g_cursor[d], 1);
        g_sorted_src[g_offsets[d] + p] = src[e];
    }
}

// ---------------- fp16 mma GEMM: BK=32, single sync/tile, ldmatrix + cp.async ----
#define SRS2 20   // smem row stride in 32-bit words (16 data + 4 pad; ldsm conflict-free)

__device__ __forceinline__ void mma_f16(float* c, const uint32_t* a, const uint32_t* b) {
    asm volatile(
        "mma.sync.aligned.m16n8k16.row.col.f32.f16.f16.f32 "
        "{%0,%1,%2,%3}, {%4,%5,%6,%7}, {%8,%9}, {%0,%1,%2,%3};"
        : "+f"(c[0]), "+f"(c[1]), "+f"(c[2]), "+f"(c[3])
        : "r"(a[0]), "r"(a[1]), "r"(a[2]), "r"(a[3]), "r"(b[0]), "r"(b[1]));
}

__device__ __forceinline__ void ldsm_x4(uint32_t* r, uint32_t saddr) {
    asm volatile("ldmatrix.sync.aligned.m8n8.x4.shared.b16 {%0,%1,%2,%3}, [%4];"
                 : "=r"(r[0]), "=r"(r[1]), "=r"(r[2]), "=r"(r[3]) : "r"(saddr));
}

__device__ __forceinline__ void cp_async16(uint32_t dst, const void* src) {
    asm volatile("cp.async.ca.shared.global [%0], [%1], 16;" :: "r"(dst), "l"(src) : "memory");
}

__device__ __forceinline__ void sts_v4(uint32_t addr, uint4 w) {
    asm volatile("st.shared.v4.b32 [%0], {%1,%2,%3,%4};"
                 :: "r"(addr), "r"(w.x), "r"(w.y), "r"(w.z), "r"(w.w) : "memory");
}

template <bool AHALF>
__global__ __launch_bounds__(256, 2) void k_gemm(const float*  __restrict__ Af,
                                                 const __half* __restrict__ Ah,
                                                 const uint32_t* __restrict__ Wt,
                                                 __half* __restrict__ C,
                                                 int M, int K) {
    __shared__ uint32_t As[2][128 * SRS2];   // [m][kp 0..15] packed fp16x2
    __shared__ uint32_t Bs[2][128 * SRS2];   // [n][kp 0..15]

    int tid  = threadIdx.x;
    int brow = blockIdx.y * 128;
    int bcol = blockIdx.x * 128;
    int Kp   = K >> 1;                       // K in fp16x2 words

    uint32_t as_base = (uint32_t)__cvta_generic_to_shared(&As[0][0]);
    uint32_t bs_base = (uint32_t)__cvta_generic_to_shared(&Bs[0][0]);
    const uint32_t BUFB = 128 * SRS2 * 4;    // bytes per buffer

    // ---- A mapping: row = tid/2, 16 k-halves per thread ----
    int arow  = tid >> 1;
    int ahalf = tid & 1;                     // 0: k 0..15 of tile, 1: k 16..31
    int gr = brow + arow;
    bool v = gr < M;
    const float*    Apf = AHALF ? nullptr : (Af + (size_t)(v ? gr : 0) * K  + ahalf * 16);
    const uint32_t* Aph = AHALF ? ((const uint32_t*)Ah + (size_t)(v ? gr : 0) * Kp + ahalf * 8) : nullptr;
    uint32_t a_st = as_base + (arow * SRS2 + ahalf * 8) * 4;

    // ---- B cp.async mapping: n = tid/2, 32B (16 k-halves) per thread (2x16B) ----
    int bn    = tid >> 1;
    int bhalf = tid & 1;
    const uint32_t* Bp = Wt + (size_t)(bcol + bn) * Kp + bhalf * 8;
    uint32_t b_st = bs_base + (bn * SRS2 + bhalf * 8) * 4;

    // ---- warp tiling: 8 warps (4m x 2n), each 32x64 ----
    int wid  = tid >> 5, lane = tid & 31;
    int wm = (wid & 3) * 32;
    int wn = (wid >> 2) * 64;
    int r  = lane >> 2;
    int cq = lane & 3;

    // ldmatrix byte offsets within a buffer (ks adds 32B = 8 words)
    uint32_t a_ld_off0 = ((wm + (lane & 15)) * SRS2 + (lane >> 4) * 4) * 4;
    uint32_t a_ld_off1 = ((wm + 16 + (lane & 15)) * SRS2 + (lane >> 4) * 4) * 4;
    int bn_in = (lane & 7) + ((lane >> 4) << 3);
    int bk_in = (lane >> 3) & 1;
    uint32_t b_ld_off[4];
    #pragma unroll
    for (int j = 0; j < 4; j++)
        b_ld_off[j] = ((wn + j * 16 + bn_in) * SRS2 + bk_in * 4) * 4;

    float acc[2][8][4];
    #pragma unroll
    for (int i = 0; i < 2; i++)
        #pragma unroll
        for (int j = 0; j < 8; j++)
            #pragma unroll
            for (int q = 0; q < 4; q++) acc[i][j][q] = 0.0f;

    float4 pa[4];   // f32 A prefetch regs (GEMM1 path only)

    // prologue: tile 0 loads
    if (AHALF) {
        cp_async16(a_st,      Aph);
        cp_async16(a_st + 16, Aph + 4);
    } else {
        #pragma unroll
        for (int i = 0; i < 4; i++)
            pa[i] = v ? *(const float4*)(Apf + i * 4) : make_float4(0,0,0,0);
    }
    cp_async16(b_st,      Bp);
    cp_async16(b_st + 16, Bp + 4);
    asm volatile("cp.async.commit_group;" ::: "memory");

    int buf = 0;
    for (int k0 = 0; k0 < K; k0 += 32) {
        if (!AHALF) {
            uint32_t ast = a_st + buf * BUFB;
            __half2 h0 = __floats2half2_rn(pa[0].x, pa[0].y);
            __half2 h1 = __floats2half2_rn(pa[0].z, pa[0].w);
            __half2 h2 = __floats2half2_rn(pa[1].x, pa[1].y);
            __half2 h3 = __floats2half2_rn(pa[1].z, pa[1].w);
            __half2 h4 = __floats2half2_rn(pa[2].x, pa[2].y);
            __half2 h5 = __floats2half2_rn(pa[2].z, pa[2].w);
            __half2 h6 = __floats2half2_rn(pa[3].x, pa[3].y);
            __half2 h7 = __floats2half2_rn(pa[3].z, pa[3].w);
            sts_v4(ast,      make_uint4(*(uint32_t*)&h0, *(uint32_t*)&h1, *(uint32_t*)&h2, *(uint32_t*)&h3));
            sts_v4(ast + 16, make_uint4(*(uint32_t*)&h4, *(uint32_t*)&h5, *(uint32_t*)&h6, *(uint32_t*)&h7));
        }

        asm volatile("cp.async.wait_group 0;" ::: "memory");   // tile k0 async loads landed
        __syncthreads();                                       // single barrier per tile

        int kn = k0 + 32;
        if (kn < K) {
            if (AHALF) {
                uint32_t adst = a_st + (buf ^ 1) * BUFB;
                cp_async16(adst,      Aph + (kn >> 1));
                cp_async16(adst + 16, Aph + (kn >> 1) + 4);
            } else {
                #pragma unroll
                for (int i = 0; i < 4; i++)
                    pa[i] = v ? *(const float4*)(Apf + kn + i * 4) : make_float4(0,0,0,0);
            }
            uint32_t bdst = b_st + (buf ^ 1) * BUFB;
            cp_async16(bdst,      Bp + (kn >> 1));
            cp_async16(bdst + 16, Bp + (kn >> 1) + 4);
            asm volatile("cp.async.commit_group;" ::: "memory");
        }

        // compute: 2 k-steps of m16n8k16
        uint32_t abase = as_base + buf * BUFB;
        uint32_t bbase = bs_base + buf * BUFB;
        #pragma unroll
        for (int ks = 0; ks < 2; ks++) {
            uint32_t koff = ks * 32;   // 8 words
            uint32_t a[2][4], b[8][2];
            ldsm_x4(a[0], abase + a_ld_off0 + koff);
            ldsm_x4(a[1], abase + a_ld_off1 + koff);
            #pragma unroll
            for (int j = 0; j < 4; j++) {
                uint32_t rr[4];
                ldsm_x4(rr, bbase + b_ld_off[j] + koff);
                b[2*j][0]   = rr[0];
                b[2*j][1]   = rr[1];
                b[2*j+1][0] = rr[2];
                b[2*j+1][1] = rr[3];
            }
            #pragma unroll
            for (int mt = 0; mt < 2; mt++)
                #pragma unroll
                for (int nt = 0; nt < 8; nt++)
                    mma_f16(acc[mt][nt], a[mt], b[nt]);
        }
        buf ^= 1;
        // no second __syncthreads(): next store targets buf^1, last read 2 iters ago
    }

    // ---- epilogue: scale by norm_src[row], convert fp16 RN, store ----
    #pragma unroll
    for (int mt = 0; mt < 2; mt++) {
        int row0 = brow + wm + mt * 16 + r;
        int row1 = row0 + 8;
        float s0 = (row0 < M) ? g_norm_src[row0] : 0.0f;
        float s1 = (row1 < M) ? g_norm_src[row1] : 0.0f;
        #pragma unroll
        for (int nt = 0; nt < 8; nt++) {
            int col = bcol + wn + nt * 8 + cq * 2;
            if (row0 < M)
                *(__half2*)(C + (size_t)row0 * HV + col) =
                    __floats2half2_rn(acc[mt][nt][0] * s0, acc[mt][nt][1] * s0);
            if (row1 < M)
                *(__half2*)(C + (size_t)row1 * HV + col) =
                    __floats2half2_rn(acc[mt][nt][2] * s1, acc[mt][nt][3] * s1);
        }
    }
}

// ---------------- aggregation: warp-per-node, uint4 (16B) lane loads ----------------
__global__ void k_agg(const __half* __restrict__ Y, const float* __restrict__ bias,
                      __half* __restrict__ O) {
    int node = blockIdx.x * 4 + (threadIdx.x >> 5);
    if (node >= NV) return;
    int lane = threadIdx.x & 31;            // 8 cols per lane via uint4
    int start = g_offsets[node];
    int cnt   = g_in_deg[node];
    const uint4* Yv = (const uint4*)Y;      // row stride = 32 uint4

    float acc[4][8];
    #pragma unroll
    for (int i = 0; i < 4; i++)
        #pragma unroll
        for (int j = 0; j < 8; j++) acc[i][j] = 0.0f;

    int e = 0;
    for (; e + 4 <= cnt; e += 4) {
        int s0 = g_sorted_src[start + e];
        int s1 = g_sorted_src[start + e + 1];
        int s2 = g_sorted_src[start + e + 2];
        int s3 = g_sorted_src[start + e + 3];
        uint4 u0 = Yv[(size_t)s0 * 32 + lane];
        uint4 u1 = Yv[(size_t)s1 * 32 + lane];
        uint4 u2 = Yv[(size_t)s2 * 32 + lane];
        uint4 u3 = Yv[(size_t)s3 * 32 + lane];
        #pragma unroll
        for (int w = 0; w < 4; w++) {
            float2 f0 = __half22float2(*((__half2*)&u0 + w));
            float2 f1 = __half22float2(*((__half2*)&u1 + w));
            float2 f2 = __half22float2(*((__half2*)&u2 + w));
            float2 f3 = __half22float2(*((__half2*)&u3 + w));
            acc[0][2*w]   += f0.x; acc[0][2*w+1] += f0.y;
            acc[1][2*w]   += f1.x; acc[1][2*w+1] += f1.y;
            acc[2][2*w]   += f2.x; acc[2][2*w+1] += f2.y;
            acc[3][2*w]   += f3.x; acc[3][2*w+1] += f3.y;
        }
    }
    for (; e < cnt; e++) {
        int s0 = g_sorted_src[start + e];
        uint4 u0 = Yv[(size_t)s0 * 32 + lane];
        #pragma unroll
        for (int w = 0; w < 4; w++) {
            float2 f0 = __half22float2(*((__half2*)&u0 + w));
            acc[0][2*w]   += f0.x; acc[0][2*w+1] += f0.y;
        }
    }
    #pragma unroll
    for (int j = 0; j < 8; j++) acc[0][j] += acc[1][j] + acc[2][j] + acc[3][j];

    float nd = g_norm_dst[node];
    float4 bb0 = *(const float4*)(bias + lane * 8);
    float4 bb1 = *(const float4*)(bias + lane * 8 + 4);
    float o[8];
    o[0] = acc[0][0] * nd + bb0.x;
    o[1] = acc[0][1] * nd + bb0.y;
    o[2] = acc[0][2] * nd + bb0.z;
    o[3] = acc[0][3] * nd + bb0.w;
    o[4] = acc[0][4] * nd + bb1.x;
    o[5] = acc[0][5] * nd + bb1.y;
    o[6] = acc[0][6] * nd + bb1.z;
    o[7] = acc[0][7] * nd + bb1.w;
    #pragma unroll
    for (int j = 0; j < 8; j++) o[j] = (o[j] >= 0.0f) ? o[j] : 0.01f * o[j];

    __half2 h0 = __floats2half2_rn(o[0], o[1]);
    __half2 h1 = __floats2half2_rn(o[2], o[3]);
    __half2 h2 = __floats2half2_rn(o[4], o[5]);
    __half2 h3 = __floats2half2_rn(o[6], o[7]);
    *(uint4*)(O + (size_t)node * HV + lane * 8) =
        make_uint4(*(uint32_t*)&h0, *(uint32_t*)&h1, *(uint32_t*)&h2, *(uint32_t*)&h3);
}

// ---------------- pooling ----------------
__device__ __forceinline__ void atomicMaxF(float* addr, float val) {
    int* ia = (int*)addr;
    int old = *ia;
    while (__int_as_float(old) < val) {
        int assumed = old;
        old = atomicCAS(ia, assumed, __float_as_int(val));
        if (old == assumed) break;
    }
}

__global__ void k_pool(const __half* __restrict__ H) {
    int t = threadIdx.x;  // 256
    float sum = 0.0f;
    float mx  = __int_as_float(0xff800000);
    for (int r = blockIdx.x; r < NV; r += gridDim.x) {
        float v = __half2float(H[(size_t)r * HV + t]);
        sum += v;
        mx = fmaxf(mx, v);
    }
    atomicAdd(&g_pooled[t], sum);
    atomicMaxF(&g_pooled[HV + t], mx);
}

__global__ void k_pick(const __half* __restrict__ H, const int* __restrict__ node_index) {
    int t = threadIdx.x;  // 256
    int ni = node_index[0];
    g_pooled[2 * HV + t] = __half2float(H[(size_t)ni * HV + t]);
}

// ---------------- head GEMV (split-k, 32 blocks, atomic partials; bias pre-seeded) ----
__global__ void k_gemv(const float* __restrict__ Wg) {
    __shared__ float sp[96];
    int t = threadIdx.x;              // 256
    int jb = blockIdx.x & 3;          // output block
    int kb = blockIdx.x >> 2;         // k chunk (8 x 96)
    for (int i = t; i < 96; i += 256) sp[i] = g_pooled[kb * 96 + i];
    __syncthreads();
    int j = jb * 256 + t;
    float acc = 0.0f;
    #pragma unroll 8
    for (int k = 0; k < 96; k++)
        acc += sp[k] * Wg[(size_t)(kb * 96 + k) * (2 * FV) + j];
    atomicAdd(&g_fd[j], acc);
}

// ---------------- epilogue: reparam + log_prob ----------------
__global__ void k_final(const float* __restrict__ eps, float* __restrict__ out) {
    __shared__ float red[FV];
    int t = threadIdx.x;  // 512
    float mu = g_fd[t];
    float sg = fabsf(g_fd[FV + t]);
    float fn = mu + sg * eps[t];
    out[t]          = fn;
    out[FV + t]     = mu;
    out[2 * FV + t] = sg;
    float z = (fn - mu) / sg;
    const float half_log2pi = 0.9189385332046727f;
    float term = -0.5f * z * z - logf(sg) - half_log2pi;
    red[t] = term;
    __syncthreads();
    #pragma unroll
    for (int o = 256; o > 0; o >>= 1) {
        if (t < o) red[t] += red[t + o];
        __syncthreads();
    }
    if (t == 0) out[3 * FV] = red[0] / (float)FV;
}

// ---------------- launch ----------------
extern "C" void kernel_launch(void* const* d_in, const int* in_sizes, int n_in,
                              void* d_out, int out_size) {
    const float* feat       = (const float*)d_in[0];
    const int*   src        = (const int*)  d_in[1];
    const int*   dst        = (const int*)  d_in[2];
    const int*   node_index = (const int*)  d_in[3];
    const float* W1         = (const float*)d_in[4];
    const float* b1         = (const float*)d_in[5];
    const float* W2         = (const float*)d_in[6];
    const float* b2         = (const float*)d_in[7];
    const float* Wg         = (const float*)d_in[8];
    const float* bg         = (const float*)d_in[9];
    const float* eps        = (const float*)d_in[10];
    float*       out        = (float*)d_out;

    void *yp_v, *hp_v, *w1p_v, *w2p_v;
    cudaGetSymbolAddress(&yp_v, g_yh);
    cudaGetSymbolAddress(&hp_v, g_hh);
    cudaGetSymbolAddress(&w1p_v, g_wt1);
    cudaGetSymbolAddress(&w2p_v, g_wt2);
    __half*   yp  = (__half*)yp_v;
    __half*   hp  = (__half*)hp_v;
    uint32_t* w1p = (uint32_t*)w1p_v;
    uint32_t* w2p = (uint32_t*)w2p_v;

    dim3 gemm_grid(2, (NV + 127) / 128);
    int agg_grid = (NV + 3) / 4;

    k_init<<<NB_SCAN + NT_W1 + NT_W2, 256>>>(W1, W2, bg);
    k_deg<<<(EV + 255) / 256, 256>>>(src, dst);
    k_norm<<<(NV + 255) / 256, 256>>>();
    // GEMM1 at launch slot #4 for the fixed-index ncu capture (control)
    k_gemm<false><<<gemm_grid, 256>>>(feat, nullptr, w1p, yp, NV, FV);
    k_scan1<<<NB_SCAN, 256>>>();
    k_scan2<<<1, 512>>>();
    k_scan3<<<NB_SCAN, 256>>>();
    k_scatter<<<(EV + 255) / 256, 256>>>(src, dst);

    k_agg<<<agg_grid, 128>>>(yp, b1, hp);
    k_gemm<true><<<gemm_grid, 256>>>(nullptr, hp, w2p, yp, NV, HV);
    k_agg<<<agg_grid, 128>>>(yp, b2, hp);

    k_pool<<<256, 256>>>(hp);
    k_pick<<<1, 256>>>(hp, node_index);
    k_gemv<<<32, 256>>>(Wg);
    k_final<<<1, 512>>>(eps, out);
}

// round 15
// speedup vs baseline: 1.0353x; 1.0188x over previous
#include <cuda_runtime.h>
#include <cuda_fp16.h>
#include <cstdint>

// Problem constants (fixed by dataset)
#define NV 100000
#define EV 1600000
#define FV 512
#define HV 256
#define NB_SCAN ((NV + 255) / 256)   // 391
#define NT_W1 64                      // (512/64) x (256/32) transpose tiles
#define NT_W2 32                      // (256/64) x (256/32)

// ---------------- scratch (static device globals; no allocation) ----------------
__device__ int   g_out_deg[NV];
__device__ int   g_in_deg[NV];
__device__ float g_norm_src[NV];
__device__ float g_norm_dst[NV];
__device__ int   g_offsets[NV];
__device__ int   g_cursor[NV];
__device__ int   g_part[NB_SCAN];
__device__ int   g_sorted_src[EV];
__device__ __align__(16) __half g_yh[(size_t)NV * HV];  // pre-aggregation activations (fp16)
__device__ __align__(16) __half g_hh[(size_t)NV * HV];  // post-aggregation activations (fp16)
__device__ __align__(16) uint32_t g_wt1[HV * (FV / 2)]; // W1^T as fp16x2: [n][k/2]
__device__ __align__(16) uint32_t g_wt2[HV * (HV / 2)]; // W2^T as fp16x2
__device__ float g_pooled[3 * HV];
__device__ float g_fd[2 * FV];

// ---------------- init: counters + fd bias seed + TILED weight transpose ----------
__global__ void k_init(const float* __restrict__ W1, const float* __restrict__ W2,
                       const float* __restrict__ bg) {
    int b = blockIdx.x;
    if (b >= NB_SCAN) {
        __shared__ float s[32][65];          // s[col(n)][row(k)] — conflict-free
        int tile = b - NB_SCAN;
        const float* W;
        uint32_t* Wtp;
        int K;
        if (tile < NT_W1) { W = W1; Wtp = g_wt1; K = FV; }
        else              { tile -= NT_W1; W = W2; Wtp = g_wt2; K = HV; }
        int kt = tile >> 3;
        int nt = tile & 7;
        int k0 = kt * 64, n0 = nt * 32;
        int t = threadIdx.x;
        #pragma unroll
        for (int j = 0; j < 8; j++) {
            int idx = t + j * 256;
            int row = idx >> 5;
            int col = idx & 31;
            s[col][row] = W[(size_t)(k0 + row) * HV + n0 + col];
        }
        __syncthreads();
        int Kp = K >> 1;
        #pragma unroll
        for (int j = 0; j < 4; j++) {
            int idx = t + j * 256;
            int n  = idx >> 5;
            int kp = idx & 31;
            __half2 h = __floats2half2_rn(s[n][2 * kp], s[n][2 * kp + 1]);
            Wtp[(size_t)(n0 + n) * Kp + (k0 >> 1) + kp] = *(uint32_t*)&h;
        }
        return;
    }
    int i = b * blockDim.x + threadIdx.x;
    if (i < NV) { g_out_deg[i] = 0; g_in_deg[i] = 0; g_cursor[i] = 0; }
    if (i < HV) { g_pooled[i] = 0.0f; g_pooled[HV + i] = __int_as_float(0xff800000); } // -inf
    if (i < 2 * FV) g_fd[i] = bg[i];
}

__global__ void k_deg(const int* __restrict__ src, const int* __restrict__ dst) {
    int e = blockIdx.x * blockDim.x + threadIdx.x;
    if (e < EV) {
        atomicAdd(&g_out_deg[src[e]], 1);
        atomicAdd(&g_in_deg[dst[e]], 1);
    }
}

__global__ void k_norm() {
    int i = blockIdx.x * blockDim.x + threadIdx.x;
    if (i < NV) {
        g_norm_src[i] = rsqrtf(fmaxf((float)g_out_deg[i], 1.0f));
        g_norm_dst[i] = rsqrtf(fmaxf((float)g_in_deg[i], 1.0f));
    }
}

// ---------------- exclusive scan of in_deg -> offsets ----------------
__global__ void k_scan1() {
    __shared__ int s[256];
    int t = threadIdx.x;
    int i = blockIdx.x * 256 + t;
    int v = (i < NV) ? g_in_deg[i] : 0;
    s[t] = v;
    __syncthreads();
    #pragma unroll
    for (int off = 1; off < 256; off <<= 1) {
        int x = (t >= off) ? s[t - off] : 0;
        __syncthreads();
        s[t] += x;
        __syncthreads();
    }
    if (i < NV) g_offsets[i] = s[t] - v;
    if (t == 255) g_part[blockIdx.x] = s[255];
}

__global__ void k_scan2() {
    __shared__ int s[512];
    int t = threadIdx.x;
    int v = (t < NB_SCAN) ? g_part[t] : 0;
    s[t] = v;
    __syncthreads();
    #pragma unroll
    for (int off = 1; off < 512; off <<= 1) {
        int x = (t >= off) ? s[t - off] : 0;
        __syncthreads();
        s[t] += x;
        __syncthreads();
    }
    if (t < NB_SCAN) g_part[t] = s[t] - v;
}

__global__ void k_scan3() {
    int t = threadIdx.x;
    int i = blockIdx.x * 256 + t;
    if (i < NV) g_offsets[i] += g_part[blockIdx.x];
}

__global__ void k_scatter(const int* __restrict__ src, const int* __restrict__ dst) {
    int e = blockIdx.x * blockDim.x + threadIdx.x;
    if (e < EV) {
        int d = dst[e];
        int p = atomicAdd(&g_cursor[d], 1);
        g_sorted_src[g_offsets[d] + p] = src[e];
    }
}

// ---------------- fp16 mma GEMM: BK=32, single sync/tile, ldmatrix + cp.async ----
#define SRS2 20   // smem row stride in 32-bit words (16 data + 4 pad; ldsm conflict-free)

__device__ __forceinline__ void mma_f16(float* c, const uint32_t* a, const uint32_t* b) {
    asm volatile(
        "mma.sync.aligned.m16n8k16.row.col.f32.f16.f16.f32 "
        "{%0,%1,%2,%3}, {%4,%5,%6,%7}, {%8,%9}, {%0,%1,%2,%3};"
        : "+f"(c[0]), "+f"(c[1]), "+f"(c[2]), "+f"(c[3])
        : "r"(a[0]), "r"(a[1]), "r"(a[2]), "r"(a[3]), "r"(b[0]), "r"(b[1]));
}

__device__ __forceinline__ void ldsm_x4(uint32_t* r, uint32_t saddr) {
    asm volatile("ldmatrix.sync.aligned.m8n8.x4.shared.b16 {%0,%1,%2,%3}, [%4];"
                 : "=r"(r[0]), "=r"(r[1]), "=r"(r[2]), "=r"(r[3]) : "r"(saddr));
}

__device__ __forceinline__ void cp_async16(uint32_t dst, const void* src) {
    asm volatile("cp.async.ca.shared.global [%0], [%1], 16;" :: "r"(dst), "l"(src) : "memory");
}

__device__ __forceinline__ void sts_v4(uint32_t addr, uint4 w) {
    asm volatile("st.shared.v4.b32 [%0], {%1,%2,%3,%4};"
                 :: "r"(addr), "r"(w.x), "r"(w.y), "r"(w.z), "r"(w.w) : "memory");
}

// streaming (evict-first) 16B global store — keeps the gathered y tensor L2-resident
__device__ __forceinline__ void stg_cs_v4(void* ptr, uint4 w) {
    asm volatile("st.global.cs.v4.b32 [%0], {%1,%2,%3,%4};"
                 :: "l"(ptr), "r"(w.x), "r"(w.y), "r"(w.z), "r"(w.w) : "memory");
}

template <bool AHALF>
__global__ __launch_bounds__(256, 2) void k_gemm(const float*  __restrict__ Af,
                                                 const __half* __restrict__ Ah,
                                                 const uint32_t* __restrict__ Wt,
                                                 __half* __restrict__ C,
                                                 int M, int K) {
    __shared__ uint32_t As[2][128 * SRS2];   // [m][kp 0..15] packed fp16x2
    __shared__ uint32_t Bs[2][128 * SRS2];   // [n][kp 0..15]

    int tid  = threadIdx.x;
    int brow = blockIdx.y * 128;
    int bcol = blockIdx.x * 128;
    int Kp   = K >> 1;                       // K in fp16x2 words

    uint32_t as_base = (uint32_t)__cvta_generic_to_shared(&As[0][0]);
    uint32_t bs_base = (uint32_t)__cvta_generic_to_shared(&Bs[0][0]);
    const uint32_t BUFB = 128 * SRS2 * 4;    // bytes per buffer

    // ---- A mapping: row = tid/2, 16 k-halves per thread ----
    int arow  = tid >> 1;
    int ahalf = tid & 1;                     // 0: k 0..15 of tile, 1: k 16..31
    int gr = brow + arow;
    bool v = gr < M;
    const float*    Apf = AHALF ? nullptr : (Af + (size_t)(v ? gr : 0) * K  + ahalf * 16);
    const uint32_t* Aph = AHALF ? ((const uint32_t*)Ah + (size_t)(v ? gr : 0) * Kp + ahalf * 8) : nullptr;
    uint32_t a_st = as_base + (arow * SRS2 + ahalf * 8) * 4;

    // ---- B cp.async mapping: n = tid/2, 32B (16 k-halves) per thread (2x16B) ----
    int bn    = tid >> 1;
    int bhalf = tid & 1;
    const uint32_t* Bp = Wt + (size_t)(bcol + bn) * Kp + bhalf * 8;
    uint32_t b_st = bs_base + (bn * SRS2 + bhalf * 8) * 4;

    // ---- warp tiling: 8 warps (4m x 2n), each 32x64 ----
    int wid  = tid >> 5, lane = tid & 31;
    int wm = (wid & 3) * 32;
    int wn = (wid >> 2) * 64;
    int r  = lane >> 2;
    int cq = lane & 3;

    // ldmatrix byte offsets within a buffer (ks adds 32B = 8 words)
    uint32_t a_ld_off0 = ((wm + (lane & 15)) * SRS2 + (lane >> 4) * 4) * 4;
    uint32_t a_ld_off1 = ((wm + 16 + (lane & 15)) * SRS2 + (lane >> 4) * 4) * 4;
    int bn_in = (lane & 7) + ((lane >> 4) << 3);
    int bk_in = (lane >> 3) & 1;
    uint32_t b_ld_off[4];
    #pragma unroll
    for (int j = 0; j < 4; j++)
        b_ld_off[j] = ((wn + j * 16 + bn_in) * SRS2 + bk_in * 4) * 4;

    float acc[2][8][4];
    #pragma unroll
    for (int i = 0; i < 2; i++)
        #pragma unroll
        for (int j = 0; j < 8; j++)
            #pragma unroll
            for (int q = 0; q < 4; q++) acc[i][j][q] = 0.0f;

    float4 pa[4];   // f32 A prefetch regs (GEMM1 path only)

    // prologue: tile 0 loads
    if (AHALF) {
        cp_async16(a_st,      Aph);
        cp_async16(a_st + 16, Aph + 4);
    } else {
        #pragma unroll
        for (int i = 0; i < 4; i++)
            pa[i] = v ? *(const float4*)(Apf + i * 4) : make_float4(0,0,0,0);
    }
    cp_async16(b_st,      Bp);
    cp_async16(b_st + 16, Bp + 4);
    asm volatile("cp.async.commit_group;" ::: "memory");

    int buf = 0;
    for (int k0 = 0; k0 < K; k0 += 32) {
        if (!AHALF) {
            uint32_t ast = a_st + buf * BUFB;
            __half2 h0 = __floats2half2_rn(pa[0].x, pa[0].y);
            __half2 h1 = __floats2half2_rn(pa[0].z, pa[0].w);
            __half2 h2 = __floats2half2_rn(pa[1].x, pa[1].y);
            __half2 h3 = __floats2half2_rn(pa[1].z, pa[1].w);
            __half2 h4 = __floats2half2_rn(pa[2].x, pa[2].y);
            __half2 h5 = __floats2half2_rn(pa[2].z, pa[2].w);
            __half2 h6 = __floats2half2_rn(pa[3].x, pa[3].y);
            __half2 h7 = __floats2half2_rn(pa[3].z, pa[3].w);
            sts_v4(ast,      make_uint4(*(uint32_t*)&h0, *(uint32_t*)&h1, *(uint32_t*)&h2, *(uint32_t*)&h3));
            sts_v4(ast + 16, make_uint4(*(uint32_t*)&h4, *(uint32_t*)&h5, *(uint32_t*)&h6, *(uint32_t*)&h7));
        }

        asm volatile("cp.async.wait_group 0;" ::: "memory");   // tile k0 async loads landed
        __syncthreads();                                       // single barrier per tile

        int kn = k0 + 32;
        if (kn < K) {
            if (AHALF) {
                uint32_t adst = a_st + (buf ^ 1) * BUFB;
                cp_async16(adst,      Aph + (kn >> 1));
                cp_async16(adst + 16, Aph + (kn >> 1) + 4);
            } else {
                #pragma unroll
                for (int i = 0; i < 4; i++)
                    pa[i] = v ? *(const float4*)(Apf + kn + i * 4) : make_float4(0,0,0,0);
            }
            uint32_t bdst = b_st + (buf ^ 1) * BUFB;
            cp_async16(bdst,      Bp + (kn >> 1));
            cp_async16(bdst + 16, Bp + (kn >> 1) + 4);
            asm volatile("cp.async.commit_group;" ::: "memory");
        }

        // compute: 2 k-steps of m16n8k16
        uint32_t abase = as_base + buf * BUFB;
        uint32_t bbase = bs_base + buf * BUFB;
        #pragma unroll
        for (int ks = 0; ks < 2; ks++) {
            uint32_t koff = ks * 32;   // 8 words
            uint32_t a[2][4], b[8][2];
            ldsm_x4(a[0], abase + a_ld_off0 + koff);
            ldsm_x4(a[1], abase + a_ld_off1 + koff);
            #pragma unroll
            for (int j = 0; j < 4; j++) {
                uint32_t rr[4];
                ldsm_x4(rr, bbase + b_ld_off[j] + koff);
                b[2*j][0]   = rr[0];
                b[2*j][1]   = rr[1];
                b[2*j+1][0] = rr[2];
                b[2*j+1][1] = rr[3];
            }
            #pragma unroll
            for (int mt = 0; mt < 2; mt++)
                #pragma unroll
                for (int nt = 0; nt < 8; nt++)
                    mma_f16(acc[mt][nt], a[mt], b[nt]);
        }
        buf ^= 1;
        // no second __syncthreads(): next store targets buf^1, last read 2 iters ago
    }

    // ---- epilogue: scale by norm_src[row], convert fp16 RN, store ----
    #pragma unroll
    for (int mt = 0; mt < 2; mt++) {
        int row0 = brow + wm + mt * 16 + r;
        int row1 = row0 + 8;
        float s0 = (row0 < M) ? g_norm_src[row0] : 0.0f;
        float s1 = (row1 < M) ? g_norm_src[row1] : 0.0f;
        #pragma unroll
        for (int nt = 0; nt < 8; nt++) {
            int col = bcol + wn + nt * 8 + cq * 2;
            if (row0 < M)
                *(__half2*)(C + (size_t)row0 * HV + col) =
                    __floats2half2_rn(acc[mt][nt][0] * s0, acc[mt][nt][1] * s0);
            if (row1 < M)
                *(__half2*)(C + (size_t)row1 * HV + col) =
                    __floats2half2_rn(acc[mt][nt][2] * s1, acc[mt][nt][3] * s1);
        }
    }
}

// ---------------- aggregation: warp-per-node, uint4 lane loads, STREAMING output ----
// h[n] = leaky( norm_dst[n] * sum_{e in CSR(n)} Y[src_e] + bias ), fp16 out via st.cs
// (evict-first store keeps the randomly-gathered Y tensor resident in L2)
__global__ void k_agg(const __half* __restrict__ Y, const float* __restrict__ bias,
                      __half* __restrict__ O) {
    int node = blockIdx.x * 4 + (threadIdx.x >> 5);
    if (node >= NV) return;
    int lane = threadIdx.x & 31;            // 8 cols per lane via uint4
    int start = g_offsets[node];
    int cnt   = g_in_deg[node];
    const uint4* Yv = (const uint4*)Y;      // row stride = 32 uint4

    float acc[4][8];
    #pragma unroll
    for (int i = 0; i < 4; i++)
        #pragma unroll
        for (int j = 0; j < 8; j++) acc[i][j] = 0.0f;

    int e = 0;
    for (; e + 4 <= cnt; e += 4) {
        int s0 = g_sorted_src[start + e];
        int s1 = g_sorted_src[start + e + 1];
        int s2 = g_sorted_src[start + e + 2];
        int s3 = g_sorted_src[start + e + 3];
        uint4 u0 = Yv[(size_t)s0 * 32 + lane];
        uint4 u1 = Yv[(size_t)s1 * 32 + lane];
        uint4 u2 = Yv[(size_t)s2 * 32 + lane];
        uint4 u3 = Yv[(size_t)s3 * 32 + lane];
        #pragma unroll
        for (int w = 0; w < 4; w++) {
            float2 f0 = __half22float2(*((__half2*)&u0 + w));
            float2 f1 = __half22float2(*((__half2*)&u1 + w));
            float2 f2 = __half22float2(*((__half2*)&u2 + w));
            float2 f3 = __half22float2(*((__half2*)&u3 + w));
            acc[0][2*w]   += f0.x; acc[0][2*w+1] += f0.y;
            acc[1][2*w]   += f1.x; acc[1][2*w+1] += f1.y;
            acc[2][2*w]   += f2.x; acc[2][2*w+1] += f2.y;
            acc[3][2*w]   += f3.x; acc[3][2*w+1] += f3.y;
        }
    }
    for (; e < cnt; e++) {
        int s0 = g_sorted_src[start + e];
        uint4 u0 = Yv[(size_t)s0 * 32 + lane];
        #pragma unroll
        for (int w = 0; w < 4; w++) {
            float2 f0 = __half22float2(*((__half2*)&u0 + w));
            acc[0][2*w]   += f0.x; acc[0][2*w+1] += f0.y;
        }
    }
    #pragma unroll
    for (int j = 0; j < 8; j++) acc[0][j] += acc[1][j] + acc[2][j] + acc[3][j];

    float nd = g_norm_dst[node];
    float4 bb0 = *(const float4*)(bias + lane * 8);
    float4 bb1 = *(const float4*)(bias + lane * 8 + 4);
    float o[8];
    o[0] = acc[0][0] * nd + bb0.x;
    o[1] = acc[0][1] * nd + bb0.y;
    o[2] = acc[0][2] * nd + bb0.z;
    o[3] = acc[0][3] * nd + bb0.w;
    o[4] = acc[0][4] * nd + bb1.x;
    o[5] = acc[0][5] * nd + bb1.y;
    o[6] = acc[0][6] * nd + bb1.z;
    o[7] = acc[0][7] * nd + bb1.w;
    #pragma unroll
    for (int j = 0; j < 8; j++) o[j] = (o[j] >= 0.0f) ? o[j] : 0.01f * o[j];

    __half2 h0 = __floats2half2_rn(o[0], o[1]);
    __half2 h1 = __floats2half2_rn(o[2], o[3]);
    __half2 h2 = __floats2half2_rn(o[4], o[5]);
    __half2 h3 = __floats2half2_rn(o[6], o[7]);
    stg_cs_v4(O + (size_t)node * HV + lane * 8,
              make_uint4(*(uint32_t*)&h0, *(uint32_t*)&h1, *(uint32_t*)&h2, *(uint32_t*)&h3));
}

// ---------------- pooling ----------------
__device__ __forceinline__ void atomicMaxF(float* addr, float val) {
    int* ia = (int*)addr;
    int old = *ia;
    while (__int_as_float(old) < val) {
        int assumed = old;
        old = atomicCAS(ia, assumed, __float_as_int(val));
        if (old == assumed) break;
    }
}

__global__ void k_pool(const __half* __restrict__ H) {
    int t = threadIdx.x;  // 256
    float sum = 0.0f;
    float mx  = __int_as_float(0xff800000);
    for (int r = blockIdx.x; r < NV; r += gridDim.x) {
        float v = __half2float(H[(size_t)r * HV + t]);
        sum += v;
        mx = fmaxf(mx, v);
    }
    atomicAdd(&g_pooled[t], sum);
    atomicMaxF(&g_pooled[HV + t], mx);
}

__global__ void k_pick(const __half* __restrict__ H, const int* __restrict__ node_index) {
    int t = threadIdx.x;  // 256
    int ni = node_index[0];
    g_pooled[2 * HV + t] = __half2float(H[(size_t)ni * HV + t]);
}

// ---------------- head GEMV (split-k, 32 blocks, atomic partials; bias pre-seeded) ----
__global__ void k_gemv(const float* __restrict__ Wg) {
    __shared__ float sp[96];
    int t = threadIdx.x;              // 256
    int jb = blockIdx.x & 3;          // output block
    int kb = blockIdx.x >> 2;         // k chunk (8 x 96)
    for (int i = t; i < 96; i += 256) sp[i] = g_pooled[kb * 96 + i];
    __syncthreads();
    int j = jb * 256 + t;
    float acc = 0.0f;
    #pragma unroll 8
    for (int k = 0; k < 96; k++)
        acc += sp[k] * Wg[(size_t)(kb * 96 + k) * (2 * FV) + j];
    atomicAdd(&g_fd[j], acc);
}

// ---------------- epilogue: reparam + log_prob ----------------
__global__ void k_final(const float* __restrict__ eps, float* __restrict__ out) {
    __shared__ float red[FV];
    int t = threadIdx.x;  // 512
    float mu = g_fd[t];
    float sg = fabsf(g_fd[FV + t]);
    float fn = mu + sg * eps[t];
    out[t]          = fn;
    out[FV + t]     = mu;
    out[2 * FV + t] = sg;
    float z = (fn - mu) / sg;
    const float half_log2pi = 0.9189385332046727f;
    float term = -0.5f * z * z - logf(sg) - half_log2pi;
    red[t] = term;
    __syncthreads();
    #pragma unroll
    for (int o = 256; o > 0; o >>= 1) {
        if (t < o) red[t] += red[t + o];
        __syncthreads();
    }
    if (t == 0) out[3 * FV] = red[0] / (float)FV;
}

// ---------------- launch ----------------
extern "C" void kernel_launch(void* const* d_in, const int* in_sizes, int n_in,
                              void* d_out, int out_size) {
    const float* feat       = (const float*)d_in[0];
    const int*   src        = (const int*)  d_in[1];
    const int*   dst        = (const int*)  d_in[2];
    const int*   node_index = (const int*)  d_in[3];
    const float* W1         = (const float*)d_in[4];
    const float* b1         = (const float*)d_in[5];
    const float* W2         = (const float*)d_in[6];
    const float* b2         = (const float*)d_in[7];
    const float* Wg         = (const float*)d_in[8];
    const float* bg         = (const float*)d_in[9];
    const float* eps        = (const float*)d_in[10];
    float*       out        = (float*)d_out;

    void *yp_v, *hp_v, *w1p_v, *w2p_v;
    cudaGetSymbolAddress(&yp_v, g_yh);
    cudaGetSymbolAddress(&hp_v, g_hh);
    cudaGetSymbolAddress(&w1p_v, g_wt1);
    cudaGetSymbolAddress(&w2p_v, g_wt2);
    __half*   yp  = (__half*)yp_v;
    __half*   hp  = (__half*)hp_v;
    uint32_t* w1p = (uint32_t*)w1p_v;
    uint32_t* w2p = (uint32_t*)w2p_v;

    dim3 gemm_grid(2, (NV + 127) / 128);
    int agg_grid = (NV + 3) / 4;

    k_init<<<NB_SCAN + NT_W1 + NT_W2, 256>>>(W1, W2, bg);
    k_deg<<<(EV + 255) / 256, 256>>>(src, dst);
    k_norm<<<(NV + 255) / 256, 256>>>();
    // GEMM1 at launch slot #4 for the fixed-index ncu capture (control)
    k_gemm<false><<<gemm_grid, 256>>>(feat, nullptr, w1p, yp, NV, FV);
    k_scan1<<<NB_SCAN, 256>>>();
    k_scan2<<<1, 512>>>();
    k_scan3<<<NB_SCAN, 256>>>();
    k_scatter<<<(EV + 255) / 256, 256>>>(src, dst);

    k_agg<<<agg_grid, 128>>>(yp, b1, hp);
    k_gemm<true><<<gemm_grid, 256>>>(nullptr, hp, w2p, yp, NV, HV);
    k_agg<<<agg_grid, 128>>>(yp, b2, hp);

    k_pool<<<256, 256>>>(hp);
    k_pick<<<1, 256>>>(hp, node_index);
    k_gemv<<<32, 256>>>(Wg);
    k_final<<<1, 512>>>(eps, out);
}

// round 16
// speedup vs baseline: 1.0485x; 1.0128x over previous
#include <cuda_runtime.h>
#include <cuda_fp16.h>
#include <cstdint>

// Problem constants (fixed by dataset)
#define NV 100000
#define EV 1600000
#define FV 512
#define HV 256
#define NB_SCAN ((NV + 255) / 256)   // 391
#define NT_W1 64                      // (512/64) x (256/32) transpose tiles
#define NT_W2 32                      // (256/64) x (256/32)

// ---------------- scratch (static device globals; no allocation) ----------------
__device__ int   g_out_deg[NV];
__device__ int   g_in_deg[NV];
__device__ float g_norm_src[NV];
__device__ float g_norm_dst[NV];
__device__ int   g_offsets[NV];
__device__ int   g_cursor[NV];
__device__ int   g_part[NB_SCAN];
__device__ int   g_sorted_src[EV];
__device__ __align__(16) __half g_yh[(size_t)NV * HV];  // pre-aggregation activations (fp16)
__device__ __align__(16) __half g_hh[(size_t)NV * HV];  // post-aggregation activations (fp16)
__device__ __align__(16) uint32_t g_wt1[HV * (FV / 2)]; // W1^T as fp16x2: [n][k/2]
__device__ __align__(16) uint32_t g_wt2[HV * (HV / 2)]; // W2^T as fp16x2
__device__ float g_pooled[3 * HV];
__device__ float g_fd[2 * FV];

// ---------------- init: counters + fd bias seed + TILED weight transpose ----------
__global__ void k_init(const float* __restrict__ W1, const float* __restrict__ W2,
                       const float* __restrict__ bg) {
    int b = blockIdx.x;
    if (b >= NB_SCAN) {
        __shared__ float s[32][65];          // s[col(n)][row(k)] — conflict-free
        int tile = b - NB_SCAN;
        const float* W;
        uint32_t* Wtp;
        int K;
        if (tile < NT_W1) { W = W1; Wtp = g_wt1; K = FV; }
        else              { tile -= NT_W1; W = W2; Wtp = g_wt2; K = HV; }
        int kt = tile >> 3;
        int nt = tile & 7;
        int k0 = kt * 64, n0 = nt * 32;
        int t = threadIdx.x;
        #pragma unroll
        for (int j = 0; j < 8; j++) {
            int idx = t + j * 256;
            int row = idx >> 5;
            int col = idx & 31;
            s[col][row] = W[(size_t)(k0 + row) * HV + n0 + col];
        }
        __syncthreads();
        int Kp = K >> 1;
        #pragma unroll
        for (int j = 0; j < 4; j++) {
            int idx = t + j * 256;
            int n  = idx >> 5;
            int kp = idx & 31;
            __half2 h = __floats2half2_rn(s[n][2 * kp], s[n][2 * kp + 1]);
            Wtp[(size_t)(n0 + n) * Kp + (k0 >> 1) + kp] = *(uint32_t*)&h;
        }
        return;
    }
    int i = b * blockDim.x + threadIdx.x;
    if (i < NV) { g_out_deg[i] = 0; g_in_deg[i] = 0; g_cursor[i] = 0; }
    if (i < HV) { g_pooled[i] = 0.0f; g_pooled[HV + i] = __int_as_float(0xff800000); } // -inf
    if (i < 2 * FV) g_fd[i] = bg[i];
}

__global__ void k_deg(const int* __restrict__ src, const int* __restrict__ dst) {
    int e = blockIdx.x * blockDim.x + threadIdx.x;
    if (e < EV) {
        atomicAdd(&g_out_deg[src[e]], 1);
        atomicAdd(&g_in_deg[dst[e]], 1);
    }
}

__global__ void k_norm() {
    int i = blockIdx.x * blockDim.x + threadIdx.x;
    if (i < NV) {
        g_norm_src[i] = rsqrtf(fmaxf((float)g_out_deg[i], 1.0f));
        g_norm_dst[i] = rsqrtf(fmaxf((float)g_in_deg[i], 1.0f));
    }
}

// ---------------- exclusive scan of in_deg -> offsets ----------------
__global__ void k_scan1() {
    __shared__ int s[256];
    int t = threadIdx.x;
    int i = blockIdx.x * 256 + t;
    int v = (i < NV) ? g_in_deg[i] : 0;
    s[t] = v;
    __syncthreads();
    #pragma unroll
    for (int off = 1; off < 256; off <<= 1) {
        int x = (t >= off) ? s[t - off] : 0;
        __syncthreads();
        s[t] += x;
        __syncthreads();
    }
    if (i < NV) g_offsets[i] = s[t] - v;
    if (t == 255) g_part[blockIdx.x] = s[255];
}

__global__ void k_scan2() {
    __shared__ int s[512];
    int t = threadIdx.x;
    int v = (t < NB_SCAN) ? g_part[t] : 0;
    s[t] = v;
    __syncthreads();
    #pragma unroll
    for (int off = 1; off < 512; off <<= 1) {
        int x = (t >= off) ? s[t - off] : 0;
        __syncthreads();
        s[t] += x;
        __syncthreads();
    }
    if (t < NB_SCAN) g_part[t] = s[t] - v;
}

__global__ void k_scan3() {
    int t = threadIdx.x;
    int i = blockIdx.x * 256 + t;
    if (i < NV) g_offsets[i] += g_part[blockIdx.x];
}

__global__ void k_scatter(const int* __restrict__ src, const int* __restrict__ dst) {
    int e = blockIdx.x * blockDim.x + threadIdx.x;
    if (e < EV) {
        int d = dst[e];
        int p = atomicAdd(&g_cursor[d], 1);
        g_sorted_src[g_offsets[d] + p] = src[e];
    }
}

// ---------------- fp16 mma GEMM: BK=32, single sync/tile, ldmatrix + cp.async ----
#define SRS2 20   // smem row stride in 32-bit words (16 data + 4 pad; ldsm conflict-free)

__device__ __forceinline__ void mma_f16(float* c, const uint32_t* a, const uint32_t* b) {
    asm volatile(
        "mma.sync.aligned.m16n8k16.row.col.f32.f16.f16.f32 "
        "{%0,%1,%2,%3}, {%4,%5,%6,%7}, {%8,%9}, {%0,%1,%2,%3};"
        : "+f"(c[0]), "+f"(c[1]), "+f"(c[2]), "+f"(c[3])
        : "r"(a[0]), "r"(a[1]), "r"(a[2]), "r"(a[3]), "r"(b[0]), "r"(b[1]));
}

__device__ __forceinline__ void ldsm_x4(uint32_t* r, uint32_t saddr) {
    asm volatile("ldmatrix.sync.aligned.m8n8.x4.shared.b16 {%0,%1,%2,%3}, [%4];"
                 : "=r"(r[0]), "=r"(r[1]), "=r"(r[2]), "=r"(r[3]) : "r"(saddr));
}

__device__ __forceinline__ void cp_async16(uint32_t dst, const void* src) {
    asm volatile("cp.async.ca.shared.global [%0], [%1], 16;" :: "r"(dst), "l"(src) : "memory");
}

__device__ __forceinline__ void sts_v4(uint32_t addr, uint4 w) {
    asm volatile("st.shared.v4.b32 [%0], {%1,%2,%3,%4};"
                 :: "r"(addr), "r"(w.x), "r"(w.y), "r"(w.z), "r"(w.w) : "memory");
}

// streaming (evict-first) 16B global store — keeps the gathered y tensor L2-resident
__device__ __forceinline__ void stg_cs_v4(void* ptr, uint4 w) {
    asm volatile("st.global.cs.v4.b32 [%0], {%1,%2,%3,%4};"
                 :: "l"(ptr), "r"(w.x), "r"(w.y), "r"(w.z), "r"(w.w) : "memory");
}

// streaming 4B global load (read-once index stream)
__device__ __forceinline__ int ldg_cs_s32(const int* ptr) {
    int v;
    asm volatile("ld.global.cs.s32 %0, [%1];" : "=r"(v) : "l"(ptr));
    return v;
}

template <bool AHALF>
__global__ __launch_bounds__(256, 2) void k_gemm(const float*  __restrict__ Af,
                                                 const __half* __restrict__ Ah,
                                                 const uint32_t* __restrict__ Wt,
                                                 __half* __restrict__ C,
                                                 int M, int K) {
    __shared__ uint32_t As[2][128 * SRS2];   // [m][kp 0..15] packed fp16x2
    __shared__ uint32_t Bs[2][128 * SRS2];   // [n][kp 0..15]

    int tid  = threadIdx.x;
    int brow = blockIdx.y * 128;
    int bcol = blockIdx.x * 128;
    int Kp   = K >> 1;                       // K in fp16x2 words

    uint32_t as_base = (uint32_t)__cvta_generic_to_shared(&As[0][0]);
    uint32_t bs_base = (uint32_t)__cvta_generic_to_shared(&Bs[0][0]);
    const uint32_t BUFB = 128 * SRS2 * 4;    // bytes per buffer

    // ---- A mapping: row = tid/2, 16 k-halves per thread ----
    int arow  = tid >> 1;
    int ahalf = tid & 1;                     // 0: k 0..15 of tile, 1: k 16..31
    int gr = brow + arow;
    bool v = gr < M;
    const float*    Apf = AHALF ? nullptr : (Af + (size_t)(v ? gr : 0) * K  + ahalf * 16);
    const uint32_t* Aph = AHALF ? ((const uint32_t*)Ah + (size_t)(v ? gr : 0) * Kp + ahalf * 8) : nullptr;
    uint32_t a_st = as_base + (arow * SRS2 + ahalf * 8) * 4;

    // ---- B cp.async mapping: n = tid/2, 32B (16 k-halves) per thread (2x16B) ----
    int bn    = tid >> 1;
    int bhalf = tid & 1;
    const uint32_t* Bp = Wt + (size_t)(bcol + bn) * Kp + bhalf * 8;
    uint32_t b_st = bs_base + (bn * SRS2 + bhalf * 8) * 4;

    // ---- warp tiling: 8 warps (4m x 2n), each 32x64 ----
    int wid  = tid >> 5, lane = tid & 31;
    int wm = (wid & 3) * 32;
    int wn = (wid >> 2) * 64;
    int r  = lane >> 2;
    int cq = lane & 3;

    // ldmatrix byte offsets within a buffer (ks adds 32B = 8 words)
    uint32_t a_ld_off0 = ((wm + (lane & 15)) * SRS2 + (lane >> 4) * 4) * 4;
    uint32_t a_ld_off1 = ((wm + 16 + (lane & 15)) * SRS2 + (lane >> 4) * 4) * 4;
    int bn_in = (lane & 7) + ((lane >> 4) << 3);
    int bk_in = (lane >> 3) & 1;
    uint32_t b_ld_off[4];
    #pragma unroll
    for (int j = 0; j < 4; j++)
        b_ld_off[j] = ((wn + j * 16 + bn_in) * SRS2 + bk_in * 4) * 4;

    float acc[2][8][4];
    #pragma unroll
    for (int i = 0; i < 2; i++)
        #pragma unroll
        for (int j = 0; j < 8; j++)
            #pragma unroll
            for (int q = 0; q < 4; q++) acc[i][j][q] = 0.0f;

    float4 pa[4];   // f32 A prefetch regs (GEMM1 path only)

    // prologue: tile 0 loads
    if (AHALF) {
        cp_async16(a_st,      Aph);
        cp_async16(a_st + 16, Aph + 4);
    } else {
        #pragma unroll
        for (int i = 0; i < 4; i++)
            pa[i] = v ? *(const float4*)(Apf + i * 4) : make_float4(0,0,0,0);
    }
    cp_async16(b_st,      Bp);
    cp_async16(b_st + 16, Bp + 4);
    asm volatile("cp.async.commit_group;" ::: "memory");

    int buf = 0;
    for (int k0 = 0; k0 < K; k0 += 32) {
        if (!AHALF) {
            uint32_t ast = a_st + buf * BUFB;
            __half2 h0 = __floats2half2_rn(pa[0].x, pa[0].y);
            __half2 h1 = __floats2half2_rn(pa[0].z, pa[0].w);
            __half2 h2 = __floats2half2_rn(pa[1].x, pa[1].y);
            __half2 h3 = __floats2half2_rn(pa[1].z, pa[1].w);
            __half2 h4 = __floats2half2_rn(pa[2].x, pa[2].y);
            __half2 h5 = __floats2half2_rn(pa[2].z, pa[2].w);
            __half2 h6 = __floats2half2_rn(pa[3].x, pa[3].y);
            __half2 h7 = __floats2half2_rn(pa[3].z, pa[3].w);
            sts_v4(ast,      make_uint4(*(uint32_t*)&h0, *(uint32_t*)&h1, *(uint32_t*)&h2, *(uint32_t*)&h3));
            sts_v4(ast + 16, make_uint4(*(uint32_t*)&h4, *(uint32_t*)&h5, *(uint32_t*)&h6, *(uint32_t*)&h7));
        }

        asm volatile("cp.async.wait_group 0;" ::: "memory");   // tile k0 async loads landed
        __syncthreads();                                       // single barrier per tile

        int kn = k0 + 32;
        if (kn < K) {
            if (AHALF) {
                uint32_t adst = a_st + (buf ^ 1) * BUFB;
                cp_async16(adst,      Aph + (kn >> 1));
                cp_async16(adst + 16, Aph + (kn >> 1) + 4);
            } else {
                #pragma unroll
                for (int i = 0; i < 4; i++)
                    pa[i] = v ? *(const float4*)(Apf + kn + i * 4) : make_float4(0,0,0,0);
            }
            uint32_t bdst = b_st + (buf ^ 1) * BUFB;
            cp_async16(bdst,      Bp + (kn >> 1));
            cp_async16(bdst + 16, Bp + (kn >> 1) + 4);
            asm volatile("cp.async.commit_group;" ::: "memory");
        }

        // compute: 2 k-steps of m16n8k16
        uint32_t abase = as_base + buf * BUFB;
        uint32_t bbase = bs_base + buf * BUFB;
        #pragma unroll
        for (int ks = 0; ks < 2; ks++) {
            uint32_t koff = ks * 32;   // 8 words
            uint32_t a[2][4], b[8][2];
            ldsm_x4(a[0], abase + a_ld_off0 + koff);
            ldsm_x4(a[1], abase + a_ld_off1 + koff);
            #pragma unroll
            for (int j = 0; j < 4; j++) {
                uint32_t rr[4];
                ldsm_x4(rr, bbase + b_ld_off[j] + koff);
                b[2*j][0]   = rr[0];
                b[2*j][1]   = rr[1];
                b[2*j+1][0] = rr[2];
                b[2*j+1][1] = rr[3];
            }
            #pragma unroll
            for (int mt = 0; mt < 2; mt++)
                #pragma unroll
                for (int nt = 0; nt < 8; nt++)
                    mma_f16(acc[mt][nt], a[mt], b[nt]);
        }
        buf ^= 1;
        // no second __syncthreads(): next store targets buf^1, last read 2 iters ago
    }

    // ---- epilogue: scale by norm_src[row], convert fp16 RN, store ----
    #pragma unroll
    for (int mt = 0; mt < 2; mt++) {
        int row0 = brow + wm + mt * 16 + r;
        int row1 = row0 + 8;
        float s0 = (row0 < M) ? g_norm_src[row0] : 0.0f;
        float s1 = (row1 < M) ? g_norm_src[row1] : 0.0f;
        #pragma unroll
        for (int nt = 0; nt < 8; nt++) {
            int col = bcol + wn + nt * 8 + cq * 2;
            if (row0 < M)
                *(__half2*)(C + (size_t)row0 * HV + col) =
                    __floats2half2_rn(acc[mt][nt][0] * s0, acc[mt][nt][1] * s0);
            if (row1 < M)
                *(__half2*)(C + (size_t)row1 * HV + col) =
                    __floats2half2_rn(acc[mt][nt][2] * s1, acc[mt][nt][3] * s1);
        }
    }
}

// ---------------- aggregation: warp-per-node, 8-edge pipelined gather ----------------
// h[n] = leaky( norm_dst[n] * sum_{e in CSR(n)} Y[src_e] + bias ), fp16 out via st.cs
__global__ __launch_bounds__(128) void k_agg(const __half* __restrict__ Y,
                                             const float* __restrict__ bias,
                                             __half* __restrict__ O) {
    int node = blockIdx.x * 4 + (threadIdx.x >> 5);
    if (node >= NV) return;
    int lane = threadIdx.x & 31;            // 8 cols per lane via uint4
    int start = g_offsets[node];
    int cnt   = g_in_deg[node];
    const uint4* Yv = (const uint4*)Y;      // row stride = 32 uint4

    float acc[4][8];
    #pragma unroll
    for (int i = 0; i < 4; i++)
        #pragma unroll
        for (int j = 0; j < 8; j++) acc[i][j] = 0.0f;

    int e = 0;
    // 8-edge pipelined batch: 8 loads in flight (MLP=8), 4 accumulator sets
    for (; e + 8 <= cnt; e += 8) {
        int s[8];
        #pragma unroll
        for (int q = 0; q < 8; q++) s[q] = ldg_cs_s32(&g_sorted_src[start + e + q]);
        uint4 u[8];
        #pragma unroll
        for (int q = 0; q < 8; q++) u[q] = Yv[(size_t)s[q] * 32 + lane];
        #pragma unroll
        for (int q = 0; q < 8; q++) {
            float* ac = acc[q & 3];
            #pragma unroll
            for (int w = 0; w < 4; w++) {
                float2 f = __half22float2(*((__half2*)&u[q] + w));
                ac[2*w] += f.x; ac[2*w+1] += f.y;
            }
        }
    }
    for (; e < cnt; e++) {
        int s0 = ldg_cs_s32(&g_sorted_src[start + e]);
        uint4 u0 = Yv[(size_t)s0 * 32 + lane];
        #pragma unroll
        for (int w = 0; w < 4; w++) {
            float2 f0 = __half22float2(*((__half2*)&u0 + w));
            acc[0][2*w] += f0.x; acc[0][2*w+1] += f0.y;
        }
    }
    #pragma unroll
    for (int j = 0; j < 8; j++) acc[0][j] += acc[1][j] + acc[2][j] + acc[3][j];

    float nd = g_norm_dst[node];
    float4 bb0 = *(const float4*)(bias + lane * 8);
    float4 bb1 = *(const float4*)(bias + lane * 8 + 4);
    float o[8];
    o[0] = acc[0][0] * nd + bb0.x;
    o[1] = acc[0][1] * nd + bb0.y;
    o[2] = acc[0][2] * nd + bb0.z;
    o[3] = acc[0][3] * nd + bb0.w;
    o[4] = acc[0][4] * nd + bb1.x;
    o[5] = acc[0][5] * nd + bb1.y;
    o[6] = acc[0][6] * nd + bb1.z;
    o[7] = acc[0][7] * nd + bb1.w;
    #pragma unroll
    for (int j = 0; j < 8; j++) o[j] = (o[j] >= 0.0f) ? o[j] : 0.01f * o[j];

    __half2 h0 = __floats2half2_rn(o[0], o[1]);
    __half2 h1 = __floats2half2_rn(o[2], o[3]);
    __half2 h2 = __floats2half2_rn(o[4], o[5]);
    __half2 h3 = __floats2half2_rn(o[6], o[7]);
    stg_cs_v4(O + (size_t)node * HV + lane * 8,
              make_uint4(*(uint32_t*)&h0, *(uint32_t*)&h1, *(uint32_t*)&h2, *(uint32_t*)&h3));
}

// ---------------- pooling ----------------
__device__ __forceinline__ void atomicMaxF(float* addr, float val) {
    int* ia = (int*)addr;
    int old = *ia;
    while (__int_as_float(old) < val) {
        int assumed = old;
        old = atomicCAS(ia, assumed, __float_as_int(val));
        if (old == assumed) break;
    }
}

__global__ void k_pool(const __half* __restrict__ H) {
    int t = threadIdx.x;  // 256
    float sum = 0.0f;
    float mx  = __int_as_float(0xff800000);
    for (int r = blockIdx.x; r < NV; r += gridDim.x) {
        float v = __half2float(H[(size_t)r * HV + t]);
        sum += v;
        mx = fmaxf(mx, v);
    }
    atomicAdd(&g_pooled[t], sum);
    atomicMaxF(&g_pooled[HV + t], mx);
}

__global__ void k_pick(const __half* __restrict__ H, const int* __restrict__ node_index) {
    int t = threadIdx.x;  // 256
    int ni = node_index[0];
    g_pooled[2 * HV + t] = __half2float(H[(size_t)ni * HV + t]);
}

// ---------------- head GEMV (split-k, 32 blocks, atomic partials; bias pre-seeded) ----
__global__ void k_gemv(const float* __restrict__ Wg) {
    __shared__ float sp[96];
    int t = threadIdx.x;              // 256
    int jb = blockIdx.x & 3;          // output block
    int kb = blockIdx.x >> 2;         // k chunk (8 x 96)
    for (int i = t; i < 96; i += 256) sp[i] = g_pooled[kb * 96 + i];
    __syncthreads();
    int j = jb * 256 + t;
    float acc = 0.0f;
    #pragma unroll 8
    for (int k = 0; k < 96; k++)
        acc += sp[k] * Wg[(size_t)(kb * 96 + k) * (2 * FV) + j];
    atomicAdd(&g_fd[j], acc);
}

// ---------------- epilogue: reparam + log_prob ----------------
__global__ void k_final(const float* __restrict__ eps, float* __restrict__ out) {
    __shared__ float red[FV];
    int t = threadIdx.x;  // 512
    float mu = g_fd[t];
    float sg = fabsf(g_fd[FV + t]);
    float fn = mu + sg * eps[t];
    out[t]          = fn;
    out[FV + t]     = mu;
    out[2 * FV + t] = sg;
    float z = (fn - mu) / sg;
    const float half_log2pi = 0.9189385332046727f;
    float term = -0.5f * z * z - logf(sg) - half_log2pi;
    red[t] = term;
    __syncthreads();
    #pragma unroll
    for (int o = 256; o > 0; o >>= 1) {
        if (t < o) red[t] += red[t + o];
        __syncthreads();
    }
    if (t == 0) out[3 * FV] = red[0] / (float)FV;
}

// ---------------- launch ----------------
extern "C" void kernel_launch(void* const* d_in, const int* in_sizes, int n_in,
                              void* d_out, int out_size) {
    const float* feat       = (const float*)d_in[0];
    const int*   src        = (const int*)  d_in[1];
    const int*   dst        = (const int*)  d_in[2];
    const int*   node_index = (const int*)  d_in[3];
    const float* W1         = (const float*)d_in[4];
    const float* b1         = (const float*)d_in[5];
    const float* W2         = (const float*)d_in[6];
    const float* b2         = (const float*)d_in[7];
    const float* Wg         = (const float*)d_in[8];
    const float* bg         = (const float*)d_in[9];
    const float* eps        = (const float*)d_in[10];
    float*       out        = (float*)d_out;

    void *yp_v, *hp_v, *w1p_v, *w2p_v;
    cudaGetSymbolAddress(&yp_v, g_yh);
    cudaGetSymbolAddress(&hp_v, g_hh);
    cudaGetSymbolAddress(&w1p_v, g_wt1);
    cudaGetSymbolAddress(&w2p_v, g_wt2);
    __half*   yp  = (__half*)yp_v;
    __half*   hp  = (__half*)hp_v;
    uint32_t* w1p = (uint32_t*)w1p_v;
    uint32_t* w2p = (uint32_t*)w2p_v;

    dim3 gemm_grid(2, (NV + 127) / 128);
    int agg_grid = (NV + 3) / 4;

    k_init<<<NB_SCAN + NT_W1 + NT_W2, 256>>>(W1, W2, bg);
    k_deg<<<(EV + 255) / 256, 256>>>(src, dst);
    k_norm<<<(NV + 255) / 256, 256>>>();
    // GEMM1 at launch slot #4 for the fixed-index ncu capture (control)
    k_gemm<false><<<gemm_grid, 256>>>(feat, nullptr, w1p, yp, NV, FV);
    k_scan1<<<NB_SCAN, 256>>>();
    k_scan2<<<1, 512>>>();
    k_scan3<<<NB_SCAN, 256>>>();
    k_scatter<<<(EV + 255) / 256, 256>>>(src, dst);

    k_agg<<<agg_grid, 128>>>(yp, b1, hp);
    k_gemm<true><<<gemm_grid, 256>>>(nullptr, hp, w2p, yp, NV, HV);
    k_agg<<<agg_grid, 128>>>(yp, b2, hp);

    k_pool<<<256, 256>>>(hp);
    k_pick<<<1, 256>>>(hp, node_index);
    k_gemv<<<32, 256>>>(Wg);
    k_final<<<1, 512>>>(eps, out);
}